// round 1
// baseline (speedup 1.0000x reference)
#include <cuda_runtime.h>

#define MAXB 64
#define MAXP 24576
#define MAXN 16
#define NC   21

// -------- scratch (no allocation allowed; __device__ globals) --------
__device__ float               g_ov[MAXB * MAXP];
__device__ int                 g_idx[MAXB * MAXP];
__device__ float               g_mine[MAXB * MAXP];
__device__ unsigned long long  g_bestprior[MAXB * MAXN];
__device__ float               g_loss_l;
__device__ float               g_loss_c;
__device__ int                 g_pos[MAXB];

// ---------------------------------------------------------------
__global__ void k_init() {
    int t = blockIdx.x * blockDim.x + threadIdx.x;
    if (t == 0) { g_loss_l = 0.f; g_loss_c = 0.f; }
    if (t < MAXB) g_pos[t] = 0;
    if (t < MAXB * MAXN) g_bestprior[t] = 0ULL;
}

// ---------------------------------------------------------------
// Per (b,p): IoU against all N truths. Track best truth per prior
// (first-max semantics) and best prior per truth (max iou, tie -> lowest p).
__global__ __launch_bounds__(256) void k_match(
    const float* __restrict__ priors,
    const float* __restrict__ truths,
    int P, int N)
{
    int b = blockIdx.y;
    int p = blockIdx.x * blockDim.x + threadIdx.x;

    __shared__ float4 s_t[MAXN];
    __shared__ float  s_area[MAXN];
    __shared__ unsigned long long s_best[MAXN];

    if (threadIdx.x < N) {
        float4 t = reinterpret_cast<const float4*>(truths)[b * N + threadIdx.x];
        s_t[threadIdx.x] = t;
        s_area[threadIdx.x] = (t.z - t.x) * (t.w - t.y);
        s_best[threadIdx.x] = 0ULL;
    }
    __syncthreads();

    if (p < P) {
        float4 pr = reinterpret_cast<const float4*>(priors)[p];
        float hx = pr.z * 0.5f, hy = pr.w * 0.5f;
        float px1 = pr.x - hx, py1 = pr.y - hy;
        float px2 = pr.x + hx, py2 = pr.y + hy;
        float area_b = (px2 - px1) * (py2 - py1);

        float best_ov = -1.0f;
        int best_n = 0;
        #pragma unroll
        for (int n = 0; n < MAXN; ++n) {
            if (n >= N) break;
            float4 t = s_t[n];
            float ltx = fmaxf(t.x, px1), lty = fmaxf(t.y, py1);
            float rbx = fminf(t.z, px2), rby = fminf(t.w, py2);
            float w = fmaxf(rbx - ltx, 0.0f);
            float h = fmaxf(rby - lty, 0.0f);
            float inter = w * h;
            float iou = inter / (s_area[n] + area_b - inter);
            if (iou > best_ov) { best_ov = iou; best_n = n; }
            unsigned long long key =
                ((unsigned long long)__float_as_uint(iou) << 32)
                | (unsigned long long)(0xFFFFFFFFu - (unsigned)p);
            if (key > s_best[n]) atomicMax(&s_best[n], key);
        }
        g_ov[(size_t)b * P + p]  = best_ov;
        g_idx[(size_t)b * P + p] = best_n;
    }
    __syncthreads();
    if (threadIdx.x < N)
        atomicMax(&g_bestprior[b * N + threadIdx.x], s_best[threadIdx.x]);
}

// ---------------------------------------------------------------
// Each truth keeps its best prior: ov=2.0, idx=n. Sequential per batch
// so duplicate best-priors resolve last-writer-wins.
__global__ void k_force(int P, int N) {
    int b = threadIdx.x;
    for (int n = 0; n < N; ++n) {
        unsigned long long key = g_bestprior[b * N + n];
        int p = (int)(0xFFFFFFFFu - (unsigned)(key & 0xFFFFFFFFull));
        g_ov[(size_t)b * P + p]  = 2.0f;
        g_idx[(size_t)b * P + p] = n;
    }
}

// ---------------------------------------------------------------
__device__ __forceinline__ float smooth_l1(float d) {
    float ad = fabsf(d);
    return (ad < 1.0f) ? 0.5f * d * d : ad - 0.5f;
}

// Per (b,p): logsumexp CE, positive loc loss, masked CE buffer, per-batch stats.
__global__ __launch_bounds__(256) void k_loss(
    const float* __restrict__ loc,
    const float* __restrict__ conf,
    const float* __restrict__ priors,
    const float* __restrict__ truths,
    const int*   __restrict__ labels,
    int P, int N)
{
    int b  = blockIdx.y;
    int p0 = blockIdx.x * 256;
    int tid = threadIdx.x;
    int p  = p0 + tid;

    __shared__ float s_conf[256 * NC];
    int nrows = min(256, P - p0);
    {
        const float* src = conf + ((size_t)b * P + p0) * NC;
        int total = nrows * NC;
        for (int i = tid; i < total; i += 256) s_conf[i] = src[i];
    }
    __syncthreads();

    float lsum = 0.f, csum = 0.f;
    int np = 0;
    if (p < P) {
        float ov = g_ov[(size_t)b * P + p];
        int  idx = g_idx[(size_t)b * P + p];
        const float* row = s_conf + tid * NC;

        float m = row[0];
        #pragma unroll
        for (int c = 1; c < NC; ++c) m = fmaxf(m, row[c]);
        float s = 0.f;
        #pragma unroll
        for (int c = 0; c < NC; ++c) s += expf(row[c] - m);
        float lse = m + logf(s);

        int ct = (ov < 0.5f) ? 0 : (labels[b * N + idx] + 1);
        float lc = lse - row[ct];

        if (ct > 0) {
            np = 1;
            csum = lc;
            float4 t  = reinterpret_cast<const float4*>(truths)[b * N + idx];
            float4 pr = reinterpret_cast<const float4*>(priors)[p];
            float gx = ((t.x + t.z) * 0.5f - pr.x) / (0.1f * pr.z);
            float gy = ((t.y + t.w) * 0.5f - pr.y) / (0.1f * pr.w);
            float gw = logf((t.z - t.x) / pr.z) / 0.2f;
            float gh = logf((t.w - t.y) / pr.w) / 0.2f;
            float4 ld = reinterpret_cast<const float4*>(loc)[(size_t)b * P + p];
            lsum = smooth_l1(ld.x - gx) + smooth_l1(ld.y - gy)
                 + smooth_l1(ld.z - gw) + smooth_l1(ld.w - gh);
            g_mine[(size_t)b * P + p] = 0.f;
        } else {
            g_mine[(size_t)b * P + p] = lc;
        }
    }

    // block reductions
    #pragma unroll
    for (int o = 16; o; o >>= 1) {
        lsum += __shfl_down_sync(0xFFFFFFFFu, lsum, o);
        csum += __shfl_down_sync(0xFFFFFFFFu, csum, o);
        np   += __shfl_down_sync(0xFFFFFFFFu, np,   o);
    }
    __shared__ float s_l[8], s_c[8];
    __shared__ int   s_n[8];
    int w = tid >> 5, lane = tid & 31;
    if (lane == 0) { s_l[w] = lsum; s_c[w] = csum; s_n[w] = np; }
    __syncthreads();
    if (tid == 0) {
        float L = 0.f, Cc = 0.f; int NN = 0;
        #pragma unroll
        for (int i = 0; i < 8; ++i) { L += s_l[i]; Cc += s_c[i]; NN += s_n[i]; }
        if (L  != 0.f) atomicAdd(&g_loss_l, L);
        if (Cc != 0.f) atomicAdd(&g_loss_c, Cc);
        if (NN != 0)   atomicAdd(&g_pos[b], NN);
    }
}

// ---------------------------------------------------------------
// Per batch: sum of the k largest masked-CE values via 31-bit bisection
// for the k-th largest (values are all >= 0 so float order == bit order).
__global__ __launch_bounds__(1024) void k_select(int P) {
    const int VPT = 24;   // 24 * 1024 = 24576 >= P
    int b = blockIdx.x;
    const float* v = g_mine + (size_t)b * P;

    float vals[VPT];
    #pragma unroll
    for (int i = 0; i < VPT; ++i) {
        int j = threadIdx.x + i * 1024;
        vals[i] = (j < P) ? v[j] : 0.f;
    }

    int k = min(3 * g_pos[b], P - 1);

    __shared__ int   s_cnt[32];
    __shared__ float s_sum[32];
    __shared__ int   s_bcast;

    unsigned T = 0u;
    for (int bit = 30; bit >= 0; --bit) {
        float cf = __uint_as_float(T | (1u << bit));
        int c = 0;
        #pragma unroll
        for (int i = 0; i < VPT; ++i) c += (vals[i] >= cf);
        #pragma unroll
        for (int o = 16; o; o >>= 1) c += __shfl_down_sync(0xFFFFFFFFu, c, o);
        if ((threadIdx.x & 31) == 0) s_cnt[threadIdx.x >> 5] = c;
        __syncthreads();
        if (threadIdx.x == 0) {
            int t = 0;
            #pragma unroll
            for (int i = 0; i < 32; ++i) t += s_cnt[i];
            s_bcast = t;
        }
        __syncthreads();
        if (s_bcast >= k) T |= (1u << bit);
    }

    float Tf = __uint_as_float(T);
    float sum = 0.f;
    int cgt = 0;
    #pragma unroll
    for (int i = 0; i < VPT; ++i) {
        if (vals[i] > Tf) { sum += vals[i]; cgt++; }
    }
    #pragma unroll
    for (int o = 16; o; o >>= 1) {
        sum += __shfl_down_sync(0xFFFFFFFFu, sum, o);
        cgt += __shfl_down_sync(0xFFFFFFFFu, cgt, o);
    }
    if ((threadIdx.x & 31) == 0) {
        s_sum[threadIdx.x >> 5] = sum;
        s_cnt[threadIdx.x >> 5] = cgt;
    }
    __syncthreads();
    if (threadIdx.x == 0) {
        float S = 0.f; int Cg = 0;
        #pragma unroll
        for (int i = 0; i < 32; ++i) { S += s_sum[i]; Cg += s_cnt[i]; }
        atomicAdd(&g_loss_c, S + (float)(k - Cg) * Tf);
    }
}

// ---------------------------------------------------------------
__global__ void k_final(float* __restrict__ out, int B) {
    float n = 0.f;
    for (int b = 0; b < B; ++b) n += (float)g_pos[b];
    out[0] = g_loss_l / n;
    out[1] = g_loss_c / n;
}

// ---------------------------------------------------------------
extern "C" void kernel_launch(void* const* d_in, const int* in_sizes, int n_in,
                              void* d_out, int out_size)
{
    const float* loc    = (const float*)d_in[0];
    const float* conf   = (const float*)d_in[1];
    const float* priors = (const float*)d_in[2];
    const float* truths = (const float*)d_in[3];
    const int*   labels = (const int*)d_in[4];

    int P = in_sizes[2] / 4;
    int B = in_sizes[0] / (4 * P);
    int N = in_sizes[3] / (4 * B);

    k_init<<<4, 256>>>();
    dim3 grid((P + 255) / 256, B);
    k_match<<<grid, 256>>>(priors, truths, P, N);
    k_force<<<1, B>>>(P, N);
    k_loss<<<grid, 256>>>(loc, conf, priors, truths, labels, P, N);
    k_select<<<B, 1024>>>(P);
    k_final<<<1, 1>>>((float*)d_out, B);
}

// round 2
// speedup vs baseline: 1.1095x; 1.1095x over previous
#include <cuda_runtime.h>

#define MAXB 64
#define MAXP 24576
#define MAXN 16
#define NC   21
#define MTPB 256      // k_match threads per block
#define MPPT 4        // priors per thread in k_match
#define MROWS (MTPB*MPPT)
#define MAXBLK 32     // max grid.x for k_match

// -------- scratch (__device__ globals; no allocation allowed) --------
__device__ int    g_match[MAXB * MAXP];          // bestn | pos<<31
__device__ float  g_mine [MAXB * MAXP];
__device__ float  g_blkI [MAXB * MAXBLK * MAXN]; // per-block best inter
__device__ float  g_blkU [MAXB * MAXBLK * MAXN]; // per-block best union
__device__ int    g_blkP [MAXB * MAXBLK * MAXN]; // per-block best prior
__device__ int    g_bestp[MAXB * MAXN];          // final best prior per truth
__device__ float  g_loss_l;
__device__ float  g_loss_c;
__device__ int    g_pos[MAXB];

// ---------------------------------------------------------------
__global__ void k_init() {
    int t = threadIdx.x;
    if (t == 0) { g_loss_l = 0.f; g_loss_c = 0.f; }
    if (t < MAXB) g_pos[t] = 0;
}

// ---------------------------------------------------------------
// Division-free matching. Carries (inter, union) pairs; all IoU compares are
// cross-multiplied: a/b > c/d  <=>  a*d > c*b   (b,d > 0 always).
__global__ __launch_bounds__(MTPB) void k_match(
    const float* __restrict__ priors,
    const float* __restrict__ truths,
    int P, int N, int nblk)
{
    int b   = blockIdx.y;
    int p0  = blockIdx.x * MROWS;
    int tid = threadIdx.x;

    __shared__ float4 s_t[MAXN];
    __shared__ float  s_area[MAXN];
    __shared__ float  s_rI[8 * MAXN];
    __shared__ float  s_rU[8 * MAXN];
    __shared__ int    s_rP[8 * MAXN];

    if (tid < N) {
        float4 t = reinterpret_cast<const float4*>(truths)[b * N + tid];
        s_t[tid] = t;
        s_area[tid] = (t.z - t.x) * (t.w - t.y);
    }
    __syncthreads();

    // per-truth best (inter, union, p) across this thread's priors
    float bi[MAXN], bu[MAXN];
    int   bp[MAXN];
    #pragma unroll
    for (int n = 0; n < MAXN; ++n) { bi[n] = 0.f; bu[n] = 1.f; bp[n] = 0x7FFFFFFF; }

    #pragma unroll
    for (int i = 0; i < MPPT; ++i) {
        int p = p0 + i * MTPB + tid;
        if (p >= P) break;
        float4 pr = reinterpret_cast<const float4*>(priors)[p];
        float hx = pr.z * 0.5f, hy = pr.w * 0.5f;
        float px1 = pr.x - hx, py1 = pr.y - hy;
        float px2 = pr.x + hx, py2 = pr.y + hy;
        float area_b = (px2 - px1) * (py2 - py1);

        float bestI = -1.f, bestU = 1.f;
        int   bestn = 0;
        #pragma unroll
        for (int n = 0; n < MAXN; ++n) {
            if (n >= N) break;
            float4 t = s_t[n];
            float w = fmaxf(fminf(t.z, px2) - fmaxf(t.x, px1), 0.f);
            float h = fmaxf(fminf(t.w, py2) - fmaxf(t.y, py1), 0.f);
            float inter = w * h;
            float uni   = s_area[n] + area_b - inter;
            // best truth for this prior (first-max)
            if (inter * bestU > bestI * uni) { bestI = inter; bestU = uni; bestn = n; }
            // best prior for this truth (max iou, tie -> lowest p)
            float l = inter * bu[n], r = bi[n] * uni;
            if (l > r || (l == r && p < bp[n])) { bi[n] = inter; bu[n] = uni; bp[n] = p; }
        }
        int pos = (2.f * bestI >= bestU) ? 1 : 0;
        g_match[(size_t)b * P + p] = bestn | (pos << 31);
    }

    // warp reduce per truth
    #pragma unroll
    for (int n = 0; n < MAXN; ++n) {
        float I = bi[n], U = bu[n]; int pp = bp[n];
        #pragma unroll
        for (int o = 16; o; o >>= 1) {
            float oI = __shfl_down_sync(0xFFFFFFFFu, I, o);
            float oU = __shfl_down_sync(0xFFFFFFFFu, U, o);
            int   oP = __shfl_down_sync(0xFFFFFFFFu, pp, o);
            float l = oI * U, r = I * oU;
            if (l > r || (l == r && oP < pp)) { I = oI; U = oU; pp = oP; }
        }
        if ((tid & 31) == 0) {
            int w = tid >> 5;
            s_rI[w * MAXN + n] = I; s_rU[w * MAXN + n] = U; s_rP[w * MAXN + n] = pp;
        }
    }
    __syncthreads();

    // cross-warp reduce: threads 0..127, groups of 8 per truth
    if (tid < 8 * MAXN) {
        int n = tid >> 3, w = tid & 7;
        float I = s_rI[w * MAXN + n], U = s_rU[w * MAXN + n];
        int   pp = s_rP[w * MAXN + n];
        #pragma unroll
        for (int o = 4; o; o >>= 1) {
            float oI = __shfl_down_sync(0xFFFFFFFFu, I, o, 8);
            float oU = __shfl_down_sync(0xFFFFFFFFu, U, o, 8);
            int   oP = __shfl_down_sync(0xFFFFFFFFu, pp, o, 8);
            float l = oI * U, r = I * oU;
            if (l > r || (l == r && oP < pp)) { I = oI; U = oU; pp = oP; }
        }
        if (w == 0) {
            size_t idx = ((size_t)b * nblk + blockIdx.x) * MAXN + n;
            g_blkI[idx] = I; g_blkU[idx] = U; g_blkP[idx] = pp;
        }
    }
}

// ---------------------------------------------------------------
// Reduce per-block candidates to the global best prior per (b, truth).
__global__ void k_reduce(int N, int nblk) {
    int b = blockIdx.x;
    int n = threadIdx.x >> 5;      // warp per truth
    int lane = threadIdx.x & 31;
    if (n >= N) return;

    float I = 0.f, U = 1.f; int pp = 0x7FFFFFFF;
    if (lane < nblk) {
        size_t idx = ((size_t)b * nblk + lane) * MAXN + n;
        I = g_blkI[idx]; U = g_blkU[idx]; pp = g_blkP[idx];
    }
    #pragma unroll
    for (int o = 16; o; o >>= 1) {
        float oI = __shfl_down_sync(0xFFFFFFFFu, I, o);
        float oU = __shfl_down_sync(0xFFFFFFFFu, U, o);
        int   oP = __shfl_down_sync(0xFFFFFFFFu, pp, o);
        float l = oI * U, r = I * oU;
        if (l > r || (l == r && oP < pp)) { I = oI; U = oU; pp = oP; }
    }
    if (lane == 0) g_bestp[b * MAXN + n] = pp;
}

// ---------------------------------------------------------------
// Each truth keeps its best prior (forced positive). Sequential per batch
// so duplicate best-priors resolve last-writer-wins.
__global__ void k_force(int P, int N) {
    int b = threadIdx.x;
    for (int n = 0; n < N; ++n) {
        int p = g_bestp[b * MAXN + n];
        g_match[(size_t)b * P + p] = n | (int)0x80000000;
    }
}

// ---------------------------------------------------------------
__device__ __forceinline__ float smooth_l1(float d) {
    float ad = fabsf(d);
    return (ad < 1.0f) ? 0.5f * d * d : ad - 0.5f;
}

__global__ __launch_bounds__(256) void k_loss(
    const float* __restrict__ loc,
    const float* __restrict__ conf,
    const float* __restrict__ priors,
    const float* __restrict__ truths,
    const int*   __restrict__ labels,
    int P, int N)
{
    int b  = blockIdx.y;
    int p0 = blockIdx.x * 256;
    int tid = threadIdx.x;
    int p  = p0 + tid;

    __shared__ float s_conf[256 * NC];
    {
        int nrows = min(256, P - p0);
        int total = nrows * NC;
        const float4* src4 = reinterpret_cast<const float4*>(conf + ((size_t)b * P + p0) * NC);
        int n4 = total >> 2;
        float4* dst4 = reinterpret_cast<float4*>(s_conf);
        for (int i = tid; i < n4; i += 256) dst4[i] = src4[i];
        for (int i = (n4 << 2) + tid; i < total; i += 256)
            s_conf[i] = conf[((size_t)b * P + p0) * NC + i];
    }
    __syncthreads();

    float lsum = 0.f, csum = 0.f;
    int np = 0;
    if (p < P) {
        int m   = g_match[(size_t)b * P + p];
        int idx = m & 0x7FFFFFFF;
        bool pos = (m < 0);
        const float* row = s_conf + tid * NC;

        float mx = row[0];
        #pragma unroll
        for (int c = 1; c < NC; ++c) mx = fmaxf(mx, row[c]);
        float s = 0.f;
        #pragma unroll
        for (int c = 0; c < NC; ++c) s += __expf(row[c] - mx);
        float lse = mx + __logf(s);

        int ct = pos ? (labels[b * N + idx] + 1) : 0;
        float lc = lse - row[ct];

        if (pos) {
            np = 1;
            csum = lc;
            float4 t  = reinterpret_cast<const float4*>(truths)[b * N + idx];
            float4 pr = reinterpret_cast<const float4*>(priors)[p];
            float gx = ((t.x + t.z) * 0.5f - pr.x) / (0.1f * pr.z);
            float gy = ((t.y + t.w) * 0.5f - pr.y) / (0.1f * pr.w);
            float gw = __logf((t.z - t.x) / pr.z) * 5.0f;
            float gh = __logf((t.w - t.y) / pr.w) * 5.0f;
            float4 ld = reinterpret_cast<const float4*>(loc)[(size_t)b * P + p];
            lsum = smooth_l1(ld.x - gx) + smooth_l1(ld.y - gy)
                 + smooth_l1(ld.z - gw) + smooth_l1(ld.w - gh);
            g_mine[(size_t)b * P + p] = 0.f;
        } else {
            g_mine[(size_t)b * P + p] = fmaxf(lc, 0.f);
        }
    }

    #pragma unroll
    for (int o = 16; o; o >>= 1) {
        lsum += __shfl_down_sync(0xFFFFFFFFu, lsum, o);
        csum += __shfl_down_sync(0xFFFFFFFFu, csum, o);
        np   += __shfl_down_sync(0xFFFFFFFFu, np,   o);
    }
    __shared__ float s_l[8], s_c[8];
    __shared__ int   s_n[8];
    int w = tid >> 5, lane = tid & 31;
    if (lane == 0) { s_l[w] = lsum; s_c[w] = csum; s_n[w] = np; }
    __syncthreads();
    if (tid == 0) {
        float L = 0.f, Cc = 0.f; int NN = 0;
        #pragma unroll
        for (int i = 0; i < 8; ++i) { L += s_l[i]; Cc += s_c[i]; NN += s_n[i]; }
        if (L  != 0.f) atomicAdd(&g_loss_l, L);
        if (Cc != 0.f) atomicAdd(&g_loss_c, Cc);
        if (NN != 0)   atomicAdd(&g_pos[b], NN);
    }
}

// ---------------------------------------------------------------
// Sum of the k largest masked-CE values per batch. Values >= 0, so float
// order == unsigned-bit order; 31-bit bisection for the exact k-th value.
// One barrier per bit via a per-bit shared counter array.
__global__ __launch_bounds__(512) void k_select(int P) {
    const int VPT = 48;   // 48 * 512 = 24576 >= P
    int b = blockIdx.x;
    int tid = threadIdx.x;
    const float* v = g_mine + (size_t)b * P;

    float vals[VPT];
    #pragma unroll
    for (int i = 0; i < VPT; ++i) {
        int j = tid + i * 512;
        vals[i] = (j < P) ? v[j] : 0.f;
    }

    int k = min(3 * g_pos[b], P - 1);

    __shared__ int   s_cnt[32];
    __shared__ float s_S;
    __shared__ int   s_C;
    if (tid < 32) s_cnt[tid] = 0;
    if (tid == 0) { s_S = 0.f; s_C = 0; }
    __syncthreads();

    unsigned T = 0u;
    for (int bit = 30; bit >= 0; --bit) {
        float cf = __uint_as_float(T | (1u << bit));
        int c = 0;
        #pragma unroll
        for (int i = 0; i < VPT; ++i) c += (vals[i] >= cf);
        #pragma unroll
        for (int o = 16; o; o >>= 1) c += __shfl_down_sync(0xFFFFFFFFu, c, o);
        if ((tid & 31) == 0) atomicAdd(&s_cnt[bit], c);
        __syncthreads();
        if (s_cnt[bit] >= k) T |= (1u << bit);
    }

    float Tf = __uint_as_float(T);
    float sum = 0.f;
    int cgt = 0;
    #pragma unroll
    for (int i = 0; i < VPT; ++i)
        if (vals[i] > Tf) { sum += vals[i]; cgt++; }
    #pragma unroll
    for (int o = 16; o; o >>= 1) {
        sum += __shfl_down_sync(0xFFFFFFFFu, sum, o);
        cgt += __shfl_down_sync(0xFFFFFFFFu, cgt, o);
    }
    if ((tid & 31) == 0) { atomicAdd(&s_S, sum); atomicAdd(&s_C, cgt); }
    __syncthreads();
    if (tid == 0)
        atomicAdd(&g_loss_c, s_S + (float)(k - s_C) * Tf);
}

// ---------------------------------------------------------------
__global__ void k_final(float* __restrict__ out, int B) {
    float n = 0.f;
    for (int b = 0; b < B; ++b) n += (float)g_pos[b];
    out[0] = g_loss_l / n;
    out[1] = g_loss_c / n;
}

// ---------------------------------------------------------------
extern "C" void kernel_launch(void* const* d_in, const int* in_sizes, int n_in,
                              void* d_out, int out_size)
{
    const float* loc    = (const float*)d_in[0];
    const float* conf   = (const float*)d_in[1];
    const float* priors = (const float*)d_in[2];
    const float* truths = (const float*)d_in[3];
    const int*   labels = (const int*)d_in[4];

    int P = in_sizes[2] / 4;
    int B = in_sizes[0] / (4 * P);
    int N = in_sizes[3] / (4 * B);

    int nblk = (P + MROWS - 1) / MROWS;

    k_init<<<1, 256>>>();
    dim3 mgrid(nblk, B);
    k_match<<<mgrid, MTPB>>>(priors, truths, P, N, nblk);
    k_reduce<<<B, 32 * ((N + 0))>>>(N, nblk);
    k_force<<<1, B>>>(P, N);
    dim3 lgrid((P + 255) / 256, B);
    k_loss<<<lgrid, 256>>>(loc, conf, priors, truths, labels, P, N);
    k_select<<<B, 512>>>(P);
    k_final<<<1, 1>>>((float*)d_out, B);
}

// round 3
// speedup vs baseline: 1.3852x; 1.2485x over previous
#include <cuda_runtime.h>
#include <cstdint>

#define MAXB    64
#define MAXN    16
#define NC      21
#define MTPB    256
#define MPPT    6
#define MROWS   (MTPB*MPPT)     // 1536
#define MAXBLK  24
#define LTPB    256
#define LSUB    4
#define LROWS   (LTPB*LSUB)     // 1024
#define MAXLBLK 32
#define MAXPP   24576

// -------- scratch (__device__ globals; fully overwritten every launch) ----
__device__ int   g_matchv[MAXB * MAXPP];           // bestn | pos<<31
__device__ float g_mine  [MAXB * MAXPP];
__device__ float g_cI[MAXB * MAXBLK * MAXN];
__device__ float g_cU[MAXB * MAXBLK * MAXN];
__device__ int   g_cP[MAXB * MAXBLK * MAXN];
__device__ int   g_fp[MAXB * MAXN];                // forced prior id (-1 = none)
__device__ int   g_fn[MAXB * MAXN];                // forced truth idx
__device__ float g_lpart[MAXB * MAXLBLK];
__device__ float g_cpart[MAXB * MAXLBLK];
__device__ int   g_npart[MAXB * MAXLBLK];
__device__ float g_bl[MAXB];
__device__ float g_bc[MAXB];
__device__ int   g_bn[MAXB];

// ---------------------------------------------------------------
// Division-free matching: all IoU compares via cross-multiplication.
__global__ __launch_bounds__(MTPB) void k_match(
    const float* __restrict__ priors,
    const float* __restrict__ truths,
    int P, int N)
{
    int b   = blockIdx.y;
    int p0  = blockIdx.x * MROWS;
    int tid = threadIdx.x;

    __shared__ float4 s_t[MAXN];
    __shared__ float  s_area[MAXN];
    __shared__ float  s_rI[8 * MAXN];
    __shared__ float  s_rU[8 * MAXN];
    __shared__ int    s_rP[8 * MAXN];

    if (tid < N) {
        float4 t = reinterpret_cast<const float4*>(truths)[b * N + tid];
        s_t[tid] = t;
        s_area[tid] = (t.z - t.x) * (t.w - t.y);
    }
    __syncthreads();

    float bi[MAXN], bu[MAXN];
    int   bp[MAXN];
    #pragma unroll
    for (int n = 0; n < MAXN; ++n) { bi[n] = -1.f; bu[n] = 1.f; bp[n] = 0x7FFFFFFF; }

    #pragma unroll
    for (int i = 0; i < MPPT; ++i) {
        int p = p0 + i * MTPB + tid;
        if (p < P) {
            float4 pr = reinterpret_cast<const float4*>(priors)[p];
            float hx = pr.z * 0.5f, hy = pr.w * 0.5f;
            float px1 = pr.x - hx, py1 = pr.y - hy;
            float px2 = pr.x + hx, py2 = pr.y + hy;
            float area_b = (px2 - px1) * (py2 - py1);

            float bestI = -1.f, bestU = 1.f;
            int   bestn = 0;
            #pragma unroll
            for (int n = 0; n < MAXN; ++n) {
                if (n < N) {
                    float4 t = s_t[n];
                    float w = fmaxf(fminf(t.z, px2) - fmaxf(t.x, px1), 0.f);
                    float h = fmaxf(fminf(t.w, py2) - fmaxf(t.y, py1), 0.f);
                    float inter = w * h;
                    float uni   = s_area[n] + area_b - inter;
                    // best truth for this prior (first-max)
                    if (inter * bestU > bestI * uni) { bestI = inter; bestU = uni; bestn = n; }
                    // best prior for this truth (max iou, tie -> lowest p)
                    float l = inter * bu[n], r = bi[n] * uni;
                    if (l > r || (l == r && p < bp[n])) { bi[n] = inter; bu[n] = uni; bp[n] = p; }
                }
            }
            int pos = (2.f * bestI >= bestU) ? 1 : 0;
            g_matchv[(size_t)b * P + p] = bestn | (pos << 31);
        }
    }

    // intra-warp reduce per truth
    #pragma unroll
    for (int n = 0; n < MAXN; ++n) {
        float I = bi[n], U = bu[n]; int pp = bp[n];
        #pragma unroll
        for (int o = 16; o; o >>= 1) {
            float oI = __shfl_down_sync(0xFFFFFFFFu, I, o);
            float oU = __shfl_down_sync(0xFFFFFFFFu, U, o);
            int   oP = __shfl_down_sync(0xFFFFFFFFu, pp, o);
            float l = oI * U, r = I * oU;
            if (l > r || (l == r && oP < pp)) { I = oI; U = oU; pp = oP; }
        }
        if ((tid & 31) == 0) {
            int w = tid >> 5;
            s_rI[w * MAXN + n] = I; s_rU[w * MAXN + n] = U; s_rP[w * MAXN + n] = pp;
        }
    }
    __syncthreads();

    // cross-warp reduce: 8 warps' candidates, groups of 8 per truth
    if (tid < 8 * MAXN) {
        int n = tid >> 3, w = tid & 7;
        float I = s_rI[w * MAXN + n], U = s_rU[w * MAXN + n];
        int   pp = s_rP[w * MAXN + n];
        #pragma unroll
        for (int o = 4; o; o >>= 1) {
            float oI = __shfl_down_sync(0xFFFFFFFFu, I, o, 8);
            float oU = __shfl_down_sync(0xFFFFFFFFu, U, o, 8);
            int   oP = __shfl_down_sync(0xFFFFFFFFu, pp, o, 8);
            float l = oI * U, r = I * oU;
            if (l > r || (l == r && oP < pp)) { I = oI; U = oU; pp = oP; }
        }
        if (w == 0) {
            size_t idx = ((size_t)b * MAXBLK + blockIdx.x) * MAXN + n;
            g_cI[idx] = I; g_cU[idx] = U; g_cP[idx] = pp;
        }
    }
}

// ---------------------------------------------------------------
// Per batch (1 warp): reduce per-block candidates -> best prior per truth,
// dedupe (last truth wins on a shared prior), emit forced table.
__global__ void k_prep(int N, int nblk) {
    int b = blockIdx.x;
    int lane = threadIdx.x;

    float I = -1.f, U = 1.f; int p = 0x7FFFFFFF;
    if (lane < N) {
        for (int j = 0; j < nblk; ++j) {
            size_t id = ((size_t)b * MAXBLK + j) * MAXN + lane;
            float oI = g_cI[id], oU = g_cU[id]; int oP = g_cP[id];
            float l = oI * U, r = I * oU;
            if (l > r || (l == r && oP < p)) { I = oI; U = oU; p = oP; }
        }
    }
    bool valid = (lane < N);
    #pragma unroll
    for (int m = 0; m < MAXN; ++m) {
        int pm = __shfl_sync(0xFFFFFFFFu, p, m);
        if (m < N && m > lane && pm == p) valid = false;
    }
    if (lane < MAXN) {
        g_fp[b * MAXN + lane] = valid ? p : -1;
        g_fn[b * MAXN + lane] = lane;
    }
}

// ---------------------------------------------------------------
__device__ __forceinline__ float smooth_l1(float d) {
    float ad = fabsf(d);
    return (ad < 1.0f) ? 0.5f * d * d : ad - 0.5f;
}

__device__ __forceinline__ void cp16(float* dst, const float4* src) {
    unsigned s = (unsigned)__cvta_generic_to_shared(dst);
    asm volatile("cp.async.cg.shared.global [%0], [%1], 16;\n" :: "r"(s), "l"(src));
}

__global__ __launch_bounds__(LTPB) void k_loss(
    const float* __restrict__ loc,
    const float* __restrict__ conf,
    const float* __restrict__ priors,
    const float* __restrict__ truths,
    const int*   __restrict__ labels,
    int P, int N, int nlb)
{
    int b   = blockIdx.y;
    int tid = threadIdx.x;
    int r0  = blockIdx.x * LROWS;
    int rows = min(LROWS, P - r0);
    int nt   = (rows + LTPB - 1) / LTPB;

    __shared__ float  s_conf[2][LTPB * NC];
    __shared__ float4 s_t[MAXN];
    __shared__ int    s_lab[MAXN], s_sfp[MAXN], s_sfn[MAXN];
    __shared__ float  s_l[8], s_c[8];
    __shared__ int    s_n[8];

    if (tid < MAXN) {
        if (tid < N) {
            s_t[tid]   = reinterpret_cast<const float4*>(truths)[b * N + tid];
            s_lab[tid] = labels[b * N + tid];
        }
        s_sfp[tid] = g_fp[b * MAXN + tid];
        s_sfn[tid] = g_fn[b * MAXN + tid];
    }

    // stage tile t into buffer t&1
    auto stage = [&](int t) {
        int tr = min(LTPB, rows - t * LTPB);
        int total = tr * NC;
        int n4 = total >> 2;
        const float* srcf = conf + ((size_t)b * P + r0 + t * LTPB) * NC;
        const float4* src4 = reinterpret_cast<const float4*>(srcf);
        float* dst = s_conf[t & 1];
        for (int i = tid; i < n4; i += LTPB) cp16(dst + i * 4, src4 + i);
        for (int i = (n4 << 2) + tid; i < total; i += LTPB) dst[i] = srcf[i];
        asm volatile("cp.async.commit_group;\n");
    };

    stage(0);

    float lsum = 0.f, csum = 0.f;
    int np = 0;

    for (int t = 0; t < nt; ++t) {
        if (t + 1 < nt) {
            stage(t + 1);
            asm volatile("cp.async.wait_group 1;\n");
        } else {
            asm volatile("cp.async.wait_group 0;\n");
        }
        __syncthreads();

        int p = r0 + t * LTPB + tid;
        if (p < P) {
            const float* row = s_conf[t & 1] + tid * NC;
            float mx = row[0];
            #pragma unroll
            for (int c = 1; c < NC; ++c) mx = fmaxf(mx, row[c]);
            float e0 = 0.f, e1 = 0.f, e2 = 0.f, e3 = 0.f;
            #pragma unroll
            for (int c = 0; c < NC; c += 4) {
                e0 += __expf(row[c] - mx);
                if (c + 1 < NC) e1 += __expf(row[c + 1] - mx);
                if (c + 2 < NC) e2 += __expf(row[c + 2] - mx);
                if (c + 3 < NC) e3 += __expf(row[c + 3] - mx);
            }
            float lse = mx + __logf((e0 + e1) + (e2 + e3));

            int mm  = g_matchv[(size_t)b * P + p];
            int idx = mm & 0x7FFFFFFF;
            bool pos = (mm < 0);
            #pragma unroll
            for (int j = 0; j < MAXN; ++j)
                if (p == s_sfp[j]) { pos = true; idx = s_sfn[j]; }

            int ct = pos ? (s_lab[idx] + 1) : 0;
            float lc = lse - row[ct];

            if (pos) {
                np++; csum += lc;
                float4 tt = s_t[idx];
                float4 pr = reinterpret_cast<const float4*>(priors)[p];
                float gx = __fdividef((tt.x + tt.z) * 0.5f - pr.x, 0.1f * pr.z);
                float gy = __fdividef((tt.y + tt.w) * 0.5f - pr.y, 0.1f * pr.w);
                float gw = __logf(__fdividef(tt.z - tt.x, pr.z)) * 5.0f;
                float gh = __logf(__fdividef(tt.w - tt.y, pr.w)) * 5.0f;
                float4 ld = reinterpret_cast<const float4*>(loc)[(size_t)b * P + p];
                lsum += smooth_l1(ld.x - gx) + smooth_l1(ld.y - gy)
                      + smooth_l1(ld.z - gw) + smooth_l1(ld.w - gh);
                g_mine[(size_t)b * P + p] = 0.f;
            } else {
                g_mine[(size_t)b * P + p] = lc;
            }
        }
        __syncthreads();  // buffer reuse guard
    }

    // block reduce partials
    #pragma unroll
    for (int o = 16; o; o >>= 1) {
        lsum += __shfl_down_sync(0xFFFFFFFFu, lsum, o);
        csum += __shfl_down_sync(0xFFFFFFFFu, csum, o);
        np   += __shfl_down_sync(0xFFFFFFFFu, np,   o);
    }
    int w = tid >> 5, lane = tid & 31;
    if (lane == 0) { s_l[w] = lsum; s_c[w] = csum; s_n[w] = np; }
    __syncthreads();
    if (tid == 0) {
        float L = 0.f, C = 0.f; int NN = 0;
        #pragma unroll
        for (int i = 0; i < 8; ++i) { L += s_l[i]; C += s_c[i]; NN += s_n[i]; }
        g_lpart[b * MAXLBLK + blockIdx.x] = L;
        g_cpart[b * MAXLBLK + blockIdx.x] = C;
        g_npart[b * MAXLBLK + blockIdx.x] = NN;
    }
}

// ---------------------------------------------------------------
// Per batch: finalize pos/L/Cpos partials, then sum of the k largest
// masked-CE values via 31-bit bisection (all values >= 0).
__global__ __launch_bounds__(512) void k_select(int P, int nlb) {
    const int VPT = 48;   // 48 * 512 = 24576 >= P
    int b = blockIdx.x;
    int tid = threadIdx.x;
    int w = tid >> 5, lane = tid & 31;
    const float* v = g_mine + (size_t)b * P;

    float vals[VPT];
    #pragma unroll
    for (int i = 0; i < VPT; ++i) {
        int j = tid + i * 512;
        vals[i] = (j < P) ? v[j] : 0.f;
    }

    __shared__ int   s_w[2][16];
    __shared__ float s_f[16];
    __shared__ float s_L, s_C;
    __shared__ int   s_k, s_np;

    if (w == 0) {
        int x   = (lane < nlb) ? g_npart[b * MAXLBLK + lane] : 0;
        float L = (lane < nlb) ? g_lpart[b * MAXLBLK + lane] : 0.f;
        float C = (lane < nlb) ? g_cpart[b * MAXLBLK + lane] : 0.f;
        x = __reduce_add_sync(0xFFFFFFFFu, x);
        #pragma unroll
        for (int o = 16; o; o >>= 1) {
            L += __shfl_down_sync(0xFFFFFFFFu, L, o);
            C += __shfl_down_sync(0xFFFFFFFFu, C, o);
        }
        if (lane == 0) { s_np = x; s_k = min(3 * x, P - 1); s_L = L; s_C = C; }
    }
    __syncthreads();
    int k = s_k;

    unsigned T = 0u;
    for (int bit = 30; bit >= 0; --bit) {
        float cf = __uint_as_float(T | (1u << bit));
        int c0 = 0, c1 = 0, c2 = 0, c3 = 0;
        #pragma unroll
        for (int i = 0; i < VPT; i += 4) {
            c0 += (vals[i]     >= cf);
            c1 += (vals[i + 1] >= cf);
            c2 += (vals[i + 2] >= cf);
            c3 += (vals[i + 3] >= cf);
        }
        int c = __reduce_add_sync(0xFFFFFFFFu, (c0 + c1) + (c2 + c3));
        if (lane == 0) s_w[bit & 1][w] = c;
        __syncthreads();
        int tot = 0;
        #pragma unroll
        for (int i = 0; i < 16; ++i) tot += s_w[bit & 1][i];
        if (tot >= k) T |= (1u << bit);
    }

    float Tf = __uint_as_float(T);
    float sum = 0.f;
    int cgt = 0;
    #pragma unroll
    for (int i = 0; i < VPT; ++i)
        if (vals[i] > Tf) { sum += vals[i]; cgt++; }
    cgt = __reduce_add_sync(0xFFFFFFFFu, cgt);
    #pragma unroll
    for (int o = 16; o; o >>= 1)
        sum += __shfl_down_sync(0xFFFFFFFFu, sum, o);
    if (lane == 0) { s_f[w] = sum; s_w[0][w] = cgt; }
    __syncthreads();
    if (tid == 0) {
        float S = 0.f; int C = 0;
        #pragma unroll
        for (int i = 0; i < 16; ++i) { S += s_f[i]; C += s_w[0][i]; }
        g_bl[b] = s_L;
        g_bc[b] = s_C + S + (float)(k - C) * Tf;
        g_bn[b] = s_np;
    }
}

// ---------------------------------------------------------------
__global__ void k_final(float* __restrict__ out, int B) {
    int t = threadIdx.x;   // 64 threads
    float l = (t < B) ? g_bl[t] : 0.f;
    float c = (t < B) ? g_bc[t] : 0.f;
    float n = (t < B) ? (float)g_bn[t] : 0.f;
    #pragma unroll
    for (int o = 16; o; o >>= 1) {
        l += __shfl_down_sync(0xFFFFFFFFu, l, o);
        c += __shfl_down_sync(0xFFFFFFFFu, c, o);
        n += __shfl_down_sync(0xFFFFFFFFu, n, o);
    }
    __shared__ float sl[2], sc[2], sn[2];
    if ((t & 31) == 0) { sl[t >> 5] = l; sc[t >> 5] = c; sn[t >> 5] = n; }
    __syncthreads();
    if (t == 0) {
        float L = sl[0] + sl[1], C = sc[0] + sc[1], NN = sn[0] + sn[1];
        out[0] = L / NN;
        out[1] = C / NN;
    }
}

// ---------------------------------------------------------------
extern "C" void kernel_launch(void* const* d_in, const int* in_sizes, int n_in,
                              void* d_out, int out_size)
{
    const float* loc    = (const float*)d_in[0];
    const float* conf   = (const float*)d_in[1];
    const float* priors = (const float*)d_in[2];
    const float* truths = (const float*)d_in[3];
    const int*   labels = (const int*)d_in[4];

    int P = in_sizes[2] / 4;
    int B = in_sizes[0] / (4 * P);
    int N = in_sizes[3] / (4 * B);

    int nblk = (P + MROWS - 1) / MROWS;   // 16
    int nlb  = (P + LROWS - 1) / LROWS;   // 24

    dim3 mgrid(nblk, B);
    k_match<<<mgrid, MTPB>>>(priors, truths, P, N);
    k_prep<<<B, 32>>>(N, nblk);
    dim3 lgrid(nlb, B);
    k_loss<<<lgrid, LTPB>>>(loc, conf, priors, truths, labels, P, N, nlb);
    k_select<<<B, 512>>>(P, nlb);
    k_final<<<1, 64>>>((float*)d_out, B);
}

// round 4
// speedup vs baseline: 1.5005x; 1.0833x over previous
#include <cuda_runtime.h>
#include <cstdint>

#define MAXB    64
#define MAXN    16
#define NC      21
#define MTPB    256
#define MPPT    6
#define MROWS   (MTPB*MPPT)     // 1536
#define MAXBLK  24
#define LTPB    256
#define LSUB    4
#define LROWS   (LTPB*LSUB)     // 1024
#define MAXLBLK 32
#define MAXPP   24576

// -------- scratch (__device__ globals; overwritten every launch) ----------
__device__ int                g_matchv[MAXB * MAXPP];   // bestn | pos<<31
__device__ float              g_mine  [MAXB * MAXPP];
__device__ unsigned long long g_cK[MAXB * MAXBLK * MAXN]; // packed (iou<<32|~p)
__device__ float              g_lpart[MAXB * MAXLBLK];
__device__ float              g_cpart[MAXB * MAXLBLK];
__device__ int                g_npart[MAXB * MAXLBLK];
__device__ float              g_bl[MAXB];
__device__ float              g_bc[MAXB];
__device__ int                g_bn[MAXB];
__device__ int                g_ctr = 0;                 // reset by last block

// ==========================================================================
// k_match: per (b,p) best-truth (stored) and per (b,truth) best-prior
// candidates (packed u64 per block). IoU via fast divide; tie rules match
// jnp.argmax (lowest index wins).
__global__ __launch_bounds__(MTPB) void k_match(
    const float* __restrict__ priors,
    const float* __restrict__ truths,
    int P, int N)
{
    int b   = blockIdx.y;
    int p0  = blockIdx.x * MROWS;
    int tid = threadIdx.x;
    int lane = tid & 31;

    __shared__ float4 s_t[MAXN];
    __shared__ float  s_area[MAXN];
    __shared__ unsigned long long s_best[MAXN];

    if (tid < MAXN) {
        s_best[tid] = 0ULL;
        if (tid < N) {
            float4 t = reinterpret_cast<const float4*>(truths)[b * N + tid];
            s_t[tid] = t;
            s_area[tid] = (t.z - t.x) * (t.w - t.y);
        }
    }
    __syncthreads();

    // load my priors
    float px1[MPPT], py1[MPPT], px2[MPPT], py2[MPPT], ab[MPPT];
    bool  vld[MPPT];
    #pragma unroll
    for (int i = 0; i < MPPT; ++i) {
        int p = p0 + i * MTPB + tid;
        vld[i] = (p < P);
        float4 pr = vld[i] ? reinterpret_cast<const float4*>(priors)[p]
                           : make_float4(0.f, 0.f, 0.f, 0.f);
        float hx = pr.z * 0.5f, hy = pr.w * 0.5f;
        px1[i] = pr.x - hx; py1[i] = pr.y - hy;
        px2[i] = pr.x + hx; py2[i] = pr.y + hy;
        ab[i]  = pr.z * pr.w;
    }

    float bt[MPPT];   // best iou per prior
    int   bn[MPPT];   // best truth per prior
    #pragma unroll
    for (int i = 0; i < MPPT; ++i) { bt[i] = -1.f; bn[i] = 0; }

    #pragma unroll
    for (int n = 0; n < MAXN; ++n) {
        if (n < N) {
            float4 t = s_t[n];
            float sa = s_area[n];
            float biou = -1.f;
            int   bp   = 0x7FFFFFFF;
            #pragma unroll
            for (int i = 0; i < MPPT; ++i) {
                float w = fmaxf(fminf(t.z, px2[i]) - fmaxf(t.x, px1[i]), 0.f);
                float h = fmaxf(fminf(t.w, py2[i]) - fmaxf(t.y, py1[i]), 0.f);
                float inter = w * h;
                float uni   = sa + ab[i] - inter;
                float iou   = vld[i] ? __fdividef(inter, uni) : -2.f;
                if (iou > bt[i]) { bt[i] = iou; bn[i] = n; }            // tie -> lowest n
                if (iou > biou)  { biou = iou; bp = p0 + i * MTPB + tid; } // tie -> lowest p
            }
            // packed key: higher iou wins; equal iou -> lowest p (via ~p)
            unsigned long long key =
                ((unsigned long long)__float_as_uint(fmaxf(biou, 0.f)) << 32)
                | (unsigned)~bp;
            #pragma unroll
            for (int o = 16; o; o >>= 1) {
                unsigned long long ok = __shfl_down_sync(0xFFFFFFFFu, key, o);
                key = (ok > key) ? ok : key;
            }
            if (lane == 0) atomicMax(&s_best[n], key);
        }
    }

    #pragma unroll
    for (int i = 0; i < MPPT; ++i) {
        int p = p0 + i * MTPB + tid;
        if (vld[i]) {
            int pos = (bt[i] >= 0.5f) ? 1 : 0;
            g_matchv[(size_t)b * P + p] = bn[i] | (pos << 31);
        }
    }
    __syncthreads();
    if (tid < MAXN)
        g_cK[((size_t)b * MAXBLK + blockIdx.x) * MAXN + tid] = s_best[tid];
}

// ==========================================================================
__device__ __forceinline__ float smooth_l1(float d) {
    float ad = fabsf(d);
    return (ad < 1.0f) ? 0.5f * d * d : ad - 0.5f;
}

__device__ __forceinline__ void cp16(float* dst, const float4* src) {
    unsigned s = (unsigned)__cvta_generic_to_shared(dst);
    asm volatile("cp.async.cg.shared.global [%0], [%1], 16;\n" :: "r"(s), "l"(src));
}

// k_loss: folds the per-truth best-prior finalization + dedupe (warp 0)
// into the prologue, then computes CE/loc losses and the mined-CE buffer.
__global__ __launch_bounds__(LTPB) void k_loss(
    const float* __restrict__ loc,
    const float* __restrict__ conf,
    const float* __restrict__ priors,
    const float* __restrict__ truths,
    const int*   __restrict__ labels,
    int P, int N, int nblk)
{
    int b   = blockIdx.y;
    int tid = threadIdx.x;
    int r0  = blockIdx.x * LROWS;
    int rows = min(LROWS, P - r0);
    int nt   = (rows + LTPB - 1) / LTPB;

    __shared__ float  s_conf[2][LTPB * NC];
    __shared__ float4 s_t[MAXN];
    __shared__ int    s_lab[MAXN], s_sfp[MAXN];
    __shared__ float  s_l[8], s_c[8];
    __shared__ int    s_n[8];

    // stage tile t into buffer t&1
    auto stage = [&](int t) {
        int tr = min(LTPB, rows - t * LTPB);
        int total = tr * NC;
        int n4 = total >> 2;
        const float* srcf = conf + ((size_t)b * P + r0 + t * LTPB) * NC;
        const float4* src4 = reinterpret_cast<const float4*>(srcf);
        float* dst = s_conf[t & 1];
        for (int i = tid; i < n4; i += LTPB) cp16(dst + i * 4, src4 + i);
        for (int i = (n4 << 2) + tid; i < total; i += LTPB) dst[i] = srcf[i];
        asm volatile("cp.async.commit_group;\n");
    };

    stage(0);

    if (tid >= 32 && tid < 32 + MAXN) {
        int j = tid - 32;
        if (j < N) {
            s_t[j]   = reinterpret_cast<const float4*>(truths)[b * N + j];
            s_lab[j] = labels[b * N + j];
        }
    }
    if (tid < 32) {
        // finalize best prior per truth + dedupe (last truth wins)
        unsigned long long best = 0ULL;
        if (tid < N)
            for (int j = 0; j < nblk; ++j) {
                unsigned long long k2 = g_cK[((size_t)b * MAXBLK + j) * MAXN + tid];
                best = (k2 > best) ? k2 : best;
            }
        int p = (tid < N) ? (int)~(unsigned)best : -1;
        bool valid = (tid < N);
        #pragma unroll
        for (int m = 0; m < MAXN; ++m) {
            int pm = __shfl_sync(0xFFFFFFFFu, p, m);
            if (m < N && m > tid && pm == p) valid = false;
        }
        if (tid < MAXN) s_sfp[tid] = valid ? p : -1;
    }

    float lsum = 0.f, csum = 0.f;
    int np = 0;

    for (int t = 0; t < nt; ++t) {
        if (t + 1 < nt) {
            stage(t + 1);
            asm volatile("cp.async.wait_group 1;\n");
        } else {
            asm volatile("cp.async.wait_group 0;\n");
        }
        __syncthreads();

        int p = r0 + t * LTPB + tid;
        if (p < P) {
            const float* row = s_conf[t & 1] + tid * NC;
            float e0 = 0.f, e1 = 0.f, e2 = 0.f, e3 = 0.f;
            #pragma unroll
            for (int c = 0; c < NC; c += 4) {
                e0 += __expf(row[c]);
                if (c + 1 < NC) e1 += __expf(row[c + 1]);
                if (c + 2 < NC) e2 += __expf(row[c + 2]);
                if (c + 3 < NC) e3 += __expf(row[c + 3]);
            }
            float lse = __logf((e0 + e1) + (e2 + e3));

            int mm  = g_matchv[(size_t)b * P + p];
            int idx = mm & 0x7FFFFFFF;
            bool pos = (mm < 0);
            #pragma unroll
            for (int j = 0; j < MAXN; ++j)
                if (p == s_sfp[j]) { pos = true; idx = j; }

            int ct = pos ? (s_lab[idx] + 1) : 0;
            float lc = lse - row[ct];

            if (pos) {
                np++; csum += lc;
                float4 tt = s_t[idx];
                float4 pr = reinterpret_cast<const float4*>(priors)[p];
                float gx = __fdividef((tt.x + tt.z) * 0.5f - pr.x, 0.1f * pr.z);
                float gy = __fdividef((tt.y + tt.w) * 0.5f - pr.y, 0.1f * pr.w);
                float gw = __logf(__fdividef(tt.z - tt.x, pr.z)) * 5.0f;
                float gh = __logf(__fdividef(tt.w - tt.y, pr.w)) * 5.0f;
                float4 ld = reinterpret_cast<const float4*>(loc)[(size_t)b * P + p];
                lsum += smooth_l1(ld.x - gx) + smooth_l1(ld.y - gy)
                      + smooth_l1(ld.z - gw) + smooth_l1(ld.w - gh);
                g_mine[(size_t)b * P + p] = 0.f;
            } else {
                g_mine[(size_t)b * P + p] = fmaxf(lc, 0.f);
            }
        }
        __syncthreads();
    }

    #pragma unroll
    for (int o = 16; o; o >>= 1) {
        lsum += __shfl_down_sync(0xFFFFFFFFu, lsum, o);
        csum += __shfl_down_sync(0xFFFFFFFFu, csum, o);
        np   += __shfl_down_sync(0xFFFFFFFFu, np,   o);
    }
    int w = tid >> 5, lane = tid & 31;
    if (lane == 0) { s_l[w] = lsum; s_c[w] = csum; s_n[w] = np; }
    __syncthreads();
    if (tid == 0) {
        float L = 0.f, C = 0.f; int NN = 0;
        #pragma unroll
        for (int i = 0; i < 8; ++i) { L += s_l[i]; C += s_c[i]; NN += s_n[i]; }
        g_lpart[b * MAXLBLK + blockIdx.x] = L;
        g_cpart[b * MAXLBLK + blockIdx.x] = C;
        g_npart[b * MAXLBLK + blockIdx.x] = NN;
    }
}

// ==========================================================================
// histogram suffix-scan: find largest bin x (of 4096) with count(bin>=x) >= k.
// Writes s_out[0]=x, s_out[1]=count(bin>x). All 512 threads participate.
__device__ __forceinline__ void find_threshold(
    int* s_hist, int k, int tid, int* s_wt, int* s_out)
{
    int w = tid >> 5, lane = tid & 31;
    int base = tid * 8;
    int l[8]; int loc = 0;
    #pragma unroll
    for (int j = 0; j < 8; ++j) { l[j] = s_hist[base + j]; loc += l[j]; }
    int incl = loc;
    #pragma unroll
    for (int o = 1; o < 32; o <<= 1) {
        int x = __shfl_up_sync(0xFFFFFFFFu, incl, o);
        if (lane >= o) incl += x;
    }
    int wsum = __shfl_sync(0xFFFFFFFFu, incl, 31);
    if (lane == 31) s_wt[w] = wsum;
    __syncthreads();
    int wa = 0;
    #pragma unroll
    for (int w2 = 0; w2 < 16; ++w2) if (w2 > w) wa += s_wt[w2];
    int above = wa + (wsum - incl);          // count in bins >= base+8
    if (above < k && above + loc >= k) {
        int run = 0;
        #pragma unroll
        for (int j = 7; j >= 0; --j) {
            run += l[j];
            if (above + run >= k) { s_out[0] = base + j; s_out[1] = above + run - l[j]; break; }
        }
    }
    __syncthreads();
}

// k_select: per batch, finalize partials + top-k sum of mined CE via
// two-level 12+12-bit histogram select. Last block reduces all batches.
__global__ __launch_bounds__(512) void k_select(int P, int nlb, float* __restrict__ out) {
    int b = blockIdx.x, tid = threadIdx.x;
    int w = tid >> 5, lane = tid & 31;

    __shared__ int   s_hist[4096];
    __shared__ int   s_wt[16];
    __shared__ int   s_out[2];
    __shared__ float s_fs[16];
    __shared__ int   s_cs[16];
    __shared__ float s_L, s_Cp;
    __shared__ int   s_k, s_np, s_last;

    // load values (order-free)
    const int V4 = 12;
    float4 v4[V4];
    {
        const float4* src = reinterpret_cast<const float4*>(g_mine + (size_t)b * P);
        int n4 = P >> 2;
        #pragma unroll
        for (int i = 0; i < V4; ++i) {
            int j = tid + i * 512;
            v4[i] = (j < n4) ? src[j] : make_float4(0.f, 0.f, 0.f, 0.f);
        }
    }
    int tail = P & 3;
    float vex = 0.f;
    if (tid < tail) vex = g_mine[(size_t)b * P + (P & ~3) + tid];

    #pragma unroll
    for (int i = 0; i < 8; ++i) s_hist[tid + i * 512] = 0;
    if (w == 0) {
        int   x = (lane < nlb) ? g_npart[b * MAXLBLK + lane] : 0;
        float L = (lane < nlb) ? g_lpart[b * MAXLBLK + lane] : 0.f;
        float C = (lane < nlb) ? g_cpart[b * MAXLBLK + lane] : 0.f;
        #pragma unroll
        for (int o = 16; o; o >>= 1) {
            x += __shfl_down_sync(0xFFFFFFFFu, x, o);
            L += __shfl_down_sync(0xFFFFFFFFu, L, o);
            C += __shfl_down_sync(0xFFFFFFFFu, C, o);
        }
        if (lane == 0) { s_np = x; s_k = min(3 * x, P - 1); s_L = L; s_Cp = C; }
    }
    __syncthreads();
    int k = s_k;

    // pass 1: histogram of top 12 value bits (bits>>19), warp-aggregated
    {
        const float* vv = reinterpret_cast<const float*>(v4);
        #pragma unroll
        for (int i = 0; i < 48; ++i) {
            unsigned bin = __float_as_uint(vv[i]) >> 19;
            unsigned m = __match_any_sync(0xFFFFFFFFu, bin);
            if (lane == (__ffs(m) - 1)) atomicAdd(&s_hist[bin], __popc(m));
        }
        if (tid < tail) atomicAdd(&s_hist[__float_as_uint(vex) >> 19], 1);
    }
    __syncthreads();
    find_threshold(s_hist, k, tid, s_wt, s_out);
    unsigned Bs = (unsigned)s_out[0];
    int c1 = s_out[1];

    #pragma unroll
    for (int i = 0; i < 8; ++i) s_hist[tid + i * 512] = 0;
    __syncthreads();

    // pass 2: next 12 bits within bin Bs
    {
        const float* vv = reinterpret_cast<const float*>(v4);
        #pragma unroll
        for (int i = 0; i < 48; ++i) {
            unsigned bits = __float_as_uint(vv[i]);
            if ((bits >> 19) == Bs) atomicAdd(&s_hist[(bits >> 7) & 0xFFF], 1);
        }
        unsigned bx = __float_as_uint(vex);
        if (tid < tail && (bx >> 19) == Bs) atomicAdd(&s_hist[(bx >> 7) & 0xFFF], 1);
    }
    __syncthreads();
    find_threshold(s_hist, k - c1, tid, s_wt, s_out);
    unsigned Ss = (unsigned)s_out[0];

    unsigned Tcut = (Bs << 12) | Ss;
    float Tf = __uint_as_float((Bs << 19) | (Ss << 7));

    float sum = 0.f; int cnt = 0;
    {
        const float* vv = reinterpret_cast<const float*>(v4);
        #pragma unroll
        for (int i = 0; i < 48; ++i) {
            unsigned bits = __float_as_uint(vv[i]);
            if ((bits >> 7) > Tcut) { sum += vv[i]; cnt++; }
        }
        unsigned bx = __float_as_uint(vex);
        if (tid < tail && (bx >> 7) > Tcut) { sum += vex; cnt++; }
    }
    #pragma unroll
    for (int o = 16; o; o >>= 1) {
        sum += __shfl_down_sync(0xFFFFFFFFu, sum, o);
        cnt += __shfl_down_sync(0xFFFFFFFFu, cnt, o);
    }
    if (lane == 0) { s_fs[w] = sum; s_cs[w] = cnt; }
    __syncthreads();
    if (tid == 0) {
        float S = 0.f; int C = 0;
        #pragma unroll
        for (int i = 0; i < 16; ++i) { S += s_fs[i]; C += s_cs[i]; }
        g_bl[b] = s_L;
        g_bc[b] = s_Cp + S + (float)(k - C) * Tf;
        g_bn[b] = s_np;
        __threadfence();
        s_last = (atomicAdd(&g_ctr, 1) == (int)gridDim.x - 1) ? 1 : 0;
    }
    __syncthreads();

    if (s_last) {
        int B = gridDim.x;
        float l = 0.f, c = 0.f, n = 0.f;
        if (tid < 64 && tid < B) {
            l = g_bl[tid]; c = g_bc[tid]; n = (float)g_bn[tid];
        }
        if (tid < 64) {
            #pragma unroll
            for (int o = 16; o; o >>= 1) {
                l += __shfl_down_sync(0xFFFFFFFFu, l, o);
                c += __shfl_down_sync(0xFFFFFFFFu, c, o);
                n += __shfl_down_sync(0xFFFFFFFFu, n, o);
            }
            if (lane == 0) { s_fs[w] = l; s_fs[w + 8] = c; s_fs[w + 4] = n; }
        }
        __syncthreads();
        if (tid == 0) {
            float L = s_fs[0] + s_fs[1];
            float C = s_fs[8] + s_fs[9];
            float NN = s_fs[4] + s_fs[5];
            out[0] = L / NN;
            out[1] = C / NN;
            g_ctr = 0;
        }
    }
}

// ==========================================================================
extern "C" void kernel_launch(void* const* d_in, const int* in_sizes, int n_in,
                              void* d_out, int out_size)
{
    const float* loc    = (const float*)d_in[0];
    const float* conf   = (const float*)d_in[1];
    const float* priors = (const float*)d_in[2];
    const float* truths = (const float*)d_in[3];
    const int*   labels = (const int*)d_in[4];

    int P = in_sizes[2] / 4;
    int B = in_sizes[0] / (4 * P);
    int N = in_sizes[3] / (4 * B);

    int nblk = (P + MROWS - 1) / MROWS;   // 16
    int nlb  = (P + LROWS - 1) / LROWS;   // 24

    dim3 mgrid(nblk, B);
    k_match<<<mgrid, MTPB>>>(priors, truths, P, N);
    dim3 lgrid(nlb, B);
    k_loss<<<lgrid, LTPB>>>(loc, conf, priors, truths, labels, P, N, nblk);
    k_select<<<B, 512>>>(P, nlb, (float*)d_out);
}

// round 5
// speedup vs baseline: 1.6356x; 1.0900x over previous
#include <cuda_runtime.h>
#include <cstdint>

#define MAXB   64
#define MAXN   16
#define NC     21
#define MTPB   256
#define MPPT   6
#define MROWS  (MTPB*MPPT)     // 1536
#define NABLK  16              // match blocks per batch (P <= 24576)
#define LTPB   256
#define LSUB   4
#define LROWS  (LTPB*LSUB)     // 1024
#define MAXPP  24576
#define CTPB   512
#define CPPT   6
#define CROWS  (CTPB*CPPT)     // 3072
#define NCBLK  8

// -------- scratch (__device__ globals; overwritten every launch) ----------
__device__ int                g_matchv[MAXB * MAXPP];   // bestn | pos<<31
__device__ float              g_mine  [MAXB * MAXPP];   // lse - row[0], 0 for pos
__device__ float              g_lse   [MAXB * MAXPP];
__device__ unsigned long long g_cK[MAXB * NABLK * MAXN];
__device__ float              g_lpart[MAXB * NCBLK];
__device__ float              g_cpart[MAXB * NCBLK];
__device__ int                g_npart[MAXB * NCBLK];
__device__ float              g_bl[MAXB];
__device__ float              g_bc[MAXB];
__device__ int                g_bn[MAXB];
__device__ int                g_ctr = 0;                // reset by last block

__device__ __forceinline__ float smooth_l1(float d) {
    float ad = fabsf(d);
    return (ad < 1.0f) ? 0.5f * d * d : ad - 0.5f;
}

__device__ __forceinline__ void cp16(float* dst, const float4* src) {
    unsigned s = (unsigned)__cvta_generic_to_shared(dst);
    asm volatile("cp.async.cg.shared.global [%0], [%1], 16;\n" :: "r"(s), "l"(src));
}

// ==========================================================================
// Fused kernel: blockIdx.x < nA  -> IoU matching (ALU-bound)
//               blockIdx.x >= nA -> logsumexp stream (DRAM-bound)
// The two roles have no data dependency and overlap on the chip.
__global__ __launch_bounds__(256) void k_fused(
    const float* __restrict__ conf,
    const float* __restrict__ priors,
    const float* __restrict__ truths,
    int P, int N, int nA)
{
    __shared__ __align__(16) float s_conf[2][LTPB * NC];   // 43 KB (lse path)
    int b   = blockIdx.y;
    int tid = threadIdx.x;

    if (blockIdx.x < nA) {
        // ================= MATCH PATH =================
        int p0   = blockIdx.x * MROWS;
        int lane = tid & 31;

        __shared__ float4 s_t[MAXN];
        __shared__ float  s_area[MAXN];
        __shared__ unsigned long long s_best[MAXN];

        if (tid < MAXN) {
            s_best[tid] = 0ULL;
            if (tid < N) {
                float4 t = reinterpret_cast<const float4*>(truths)[b * N + tid];
                s_t[tid] = t;
                s_area[tid] = (t.z - t.x) * (t.w - t.y);
            }
        }
        __syncthreads();

        float px1[MPPT], py1[MPPT], px2[MPPT], py2[MPPT], ab[MPPT];
        #pragma unroll
        for (int i = 0; i < MPPT; ++i) {
            int p  = p0 + i * MTPB + tid;
            int pc = min(p, P - 1);                 // clamp; dup candidates lose ties
            float4 pr = reinterpret_cast<const float4*>(priors)[pc];
            float hx = pr.z * 0.5f, hy = pr.w * 0.5f;
            px1[i] = pr.x - hx; py1[i] = pr.y - hy;
            px2[i] = pr.x + hx; py2[i] = pr.y + hy;
            ab[i]  = pr.z * pr.w;
        }

        float bt[MPPT];
        int   bn[MPPT];
        #pragma unroll
        for (int i = 0; i < MPPT; ++i) { bt[i] = -1.f; bn[i] = 0; }

        #pragma unroll
        for (int n = 0; n < MAXN; ++n) {
            if (n < N) {
                float4 t = s_t[n];
                float sa = s_area[n];
                float biou = -1.f;
                int   bp   = 0x7FFFFFFF;
                #pragma unroll
                for (int i = 0; i < MPPT; ++i) {
                    float w = fmaxf(fminf(t.z, px2[i]) - fmaxf(t.x, px1[i]), 0.f);
                    float h = fmaxf(fminf(t.w, py2[i]) - fmaxf(t.y, py1[i]), 0.f);
                    float inter = w * h;
                    float uni   = sa + ab[i] - inter;
                    float iou   = __fdividef(inter, uni);
                    if (iou > bt[i]) { bt[i] = iou; bn[i] = n; }             // tie -> lowest n
                    if (iou > biou)  { biou = iou; bp = p0 + i * MTPB + tid; } // tie -> lowest p
                }
                unsigned long long key =
                    ((unsigned long long)__float_as_uint(fmaxf(biou, 0.f)) << 32)
                    | (unsigned)~bp;
                #pragma unroll
                for (int o = 16; o; o >>= 1) {
                    unsigned long long ok = __shfl_down_sync(0xFFFFFFFFu, key, o);
                    key = (ok > key) ? ok : key;
                }
                if (lane == 0) atomicMax(&s_best[n], key);
            }
        }

        #pragma unroll
        for (int i = 0; i < MPPT; ++i) {
            int p = p0 + i * MTPB + tid;
            if (p < P) {
                int pos = (bt[i] >= 0.5f) ? 1 : 0;
                g_matchv[(size_t)b * P + p] = bn[i] | (pos << 31);
            }
        }
        __syncthreads();
        if (tid < MAXN)
            g_cK[((size_t)b * NABLK + blockIdx.x) * MAXN + tid] = s_best[tid];

    } else {
        // ================= LSE PATH =================
        int bx = blockIdx.x - nA;
        int r0 = bx * LROWS;
        int rows = min(LROWS, P - r0);
        int nt = (rows + LTPB - 1) / LTPB;

        auto stage = [&](int t) {
            int tr = min(LTPB, rows - t * LTPB);
            int total = tr * NC;
            int n4 = total >> 2;
            const float* srcf = conf + ((size_t)b * P + r0 + t * LTPB) * NC;
            const float4* src4 = reinterpret_cast<const float4*>(srcf);
            float* dst = s_conf[t & 1];
            for (int i = tid; i < n4; i += LTPB) cp16(dst + i * 4, src4 + i);
            for (int i = (n4 << 2) + tid; i < total; i += LTPB) dst[i] = srcf[i];
            asm volatile("cp.async.commit_group;\n");
        };

        stage(0);
        for (int t = 0; t < nt; ++t) {
            if (t + 1 < nt) {
                stage(t + 1);
                asm volatile("cp.async.wait_group 1;\n");
            } else {
                asm volatile("cp.async.wait_group 0;\n");
            }
            __syncthreads();

            int p = r0 + t * LTPB + tid;
            if (p < P) {
                const float* row = s_conf[t & 1] + tid * NC;
                float e0 = 0.f, e1 = 0.f, e2 = 0.f, e3 = 0.f;
                #pragma unroll
                for (int c = 0; c < NC; c += 4) {
                    e0 += __expf(row[c]);
                    if (c + 1 < NC) e1 += __expf(row[c + 1]);
                    if (c + 2 < NC) e2 += __expf(row[c + 2]);
                    if (c + 3 < NC) e3 += __expf(row[c + 3]);
                }
                float lse = __logf((e0 + e1) + (e2 + e3));
                g_lse [(size_t)b * P + p] = lse;
                g_mine[(size_t)b * P + p] = lse - row[0];   // >= 0 always
            }
            __syncthreads();
        }
    }
}

// ==========================================================================
// k_post: streaming pass over match words. Positives (match bit) accumulate
// CE/loc partials and zero their mined-CE entry. No forced-prior knowledge.
__global__ __launch_bounds__(CTPB) void k_post(
    const float* __restrict__ loc,
    const float* __restrict__ conf,
    const float* __restrict__ priors,
    const float* __restrict__ truths,
    const int*   __restrict__ labels,
    int P, int N)
{
    int b   = blockIdx.y;
    int tid = threadIdx.x;
    int r0  = blockIdx.x * CROWS;

    __shared__ float4 s_t[MAXN];
    __shared__ int    s_lab[MAXN];
    __shared__ float  s_l[16], s_c[16];
    __shared__ int    s_n[16];

    if (tid < N) {
        s_t[tid]   = reinterpret_cast<const float4*>(truths)[b * N + tid];
        s_lab[tid] = labels[b * N + tid];
    }
    __syncthreads();

    float lsum = 0.f, csum = 0.f;
    int np = 0;
    #pragma unroll
    for (int j = 0; j < CPPT; ++j) {
        int p = r0 + j * CTPB + tid;
        if (p < P) {
            int mm = g_matchv[(size_t)b * P + p];
            if (mm < 0) {
                int bnn = mm & 0x7FFFFFFF;
                float lse = g_lse[(size_t)b * P + p];
                const float* crow = conf + ((size_t)b * P + p) * NC;
                csum += lse - crow[s_lab[bnn] + 1];
                np++;
                float4 tt = s_t[bnn];
                float4 pr = reinterpret_cast<const float4*>(priors)[p];
                float gx = __fdividef((tt.x + tt.z) * 0.5f - pr.x, 0.1f * pr.z);
                float gy = __fdividef((tt.y + tt.w) * 0.5f - pr.y, 0.1f * pr.w);
                float gw = __logf(__fdividef(tt.z - tt.x, pr.z)) * 5.0f;
                float gh = __logf(__fdividef(tt.w - tt.y, pr.w)) * 5.0f;
                float4 ld = reinterpret_cast<const float4*>(loc)[(size_t)b * P + p];
                lsum += smooth_l1(ld.x - gx) + smooth_l1(ld.y - gy)
                      + smooth_l1(ld.z - gw) + smooth_l1(ld.w - gh);
                g_mine[(size_t)b * P + p] = 0.f;
            }
        }
    }

    #pragma unroll
    for (int o = 16; o; o >>= 1) {
        lsum += __shfl_down_sync(0xFFFFFFFFu, lsum, o);
        csum += __shfl_down_sync(0xFFFFFFFFu, csum, o);
        np   += __shfl_down_sync(0xFFFFFFFFu, np,   o);
    }
    int w = tid >> 5, lane = tid & 31;
    if (lane == 0) { s_l[w] = lsum; s_c[w] = csum; s_n[w] = np; }
    __syncthreads();
    if (tid == 0) {
        float L = 0.f, C = 0.f; int NN = 0;
        #pragma unroll
        for (int i = 0; i < 16; ++i) { L += s_l[i]; C += s_c[i]; NN += s_n[i]; }
        g_lpart[b * NCBLK + blockIdx.x] = L;
        g_cpart[b * NCBLK + blockIdx.x] = C;
        g_npart[b * NCBLK + blockIdx.x] = NN;
    }
}

// ==========================================================================
__device__ __forceinline__ void find_threshold(
    int* s_hist, int k, int tid, int* s_wt, int* s_out)
{
    int w = tid >> 5, lane = tid & 31;
    int base = tid * 8;
    int l[8]; int loc = 0;
    #pragma unroll
    for (int j = 0; j < 8; ++j) { l[j] = s_hist[base + j]; loc += l[j]; }
    int incl = loc;
    #pragma unroll
    for (int o = 1; o < 32; o <<= 1) {
        int x = __shfl_up_sync(0xFFFFFFFFu, incl, o);
        if (lane >= o) incl += x;
    }
    int wsum = __shfl_sync(0xFFFFFFFFu, incl, 31);
    if (lane == 31) s_wt[w] = wsum;
    __syncthreads();
    int wa = 0;
    #pragma unroll
    for (int w2 = 0; w2 < 16; ++w2) if (w2 > w) wa += s_wt[w2];
    int above = wa + (wsum - incl);
    if (above < k && above + loc >= k) {
        int run = 0;
        #pragma unroll
        for (int j = 7; j >= 0; --j) {
            run += l[j];
            if (above + run >= k) { s_out[0] = base + j; s_out[1] = above + run - l[j]; break; }
        }
    }
    __syncthreads();
}

// k_select: per batch — prologue (warp 0) finalizes partials, applies the
// <=16 forced-prior corrections (add forced CE/loc, subtract double-counted
// match-positive versions, scatter-zero g_mine); then two-level 12+12-bit
// histogram top-k sum of mined CE. Last block reduces all batches.
__global__ __launch_bounds__(512) void k_select(
    const float* __restrict__ loc,
    const float* __restrict__ conf,
    const float* __restrict__ priors,
    const float* __restrict__ truths,
    const int*   __restrict__ labels,
    int P, int N, int nA, float* __restrict__ out)
{
    int b = blockIdx.x, tid = threadIdx.x;
    int w = tid >> 5, lane = tid & 31;

    __shared__ int   s_hist[4096];
    __shared__ int   s_wt[16];
    __shared__ int   s_out[2];
    __shared__ float s_fs[16];
    __shared__ int   s_cs[16];
    __shared__ float s_L, s_Cp;
    __shared__ int   s_k, s_np, s_last;

    #pragma unroll
    for (int i = 0; i < 8; ++i) s_hist[tid + i * 512] = 0;

    if (w == 0) {
        // partials
        float L = 0.f, C = 0.f; int n = 0;
        if (lane < NCBLK) {
            L = g_lpart[b * NCBLK + lane];
            C = g_cpart[b * NCBLK + lane];
            n = g_npart[b * NCBLK + lane];
        }
        // forced best prior per truth + dedupe (last truth wins)
        unsigned long long best = 0ULL;
        if (lane < N)
            for (int j = 0; j < nA; ++j) {
                unsigned long long k2 = g_cK[((size_t)b * NABLK + j) * MAXN + lane];
                best = (k2 > best) ? k2 : best;
            }
        int fp = (lane < N) ? (int)~(unsigned)best : -1;
        bool valid = (lane < N);
        #pragma unroll
        for (int m = 0; m < MAXN; ++m) {
            int pm = __shfl_sync(0xFFFFFFFFu, fp, m);
            if (m < N && m > lane && pm == fp) valid = false;
        }
        if (valid) {
            int p = fp;
            int mm = g_matchv[(size_t)b * P + p];
            float lse = g_lse[(size_t)b * P + p];
            const float* crow = conf + ((size_t)b * P + p) * NC;
            float4 pr = reinterpret_cast<const float4*>(priors)[p];
            float4 ld = reinterpret_cast<const float4*>(loc)[(size_t)b * P + p];
            float izx = __fdividef(1.f, 0.1f * pr.z);
            float izy = __fdividef(1.f, 0.1f * pr.w);

            // add forced contribution (truth = lane)
            {
                float4 tt = reinterpret_cast<const float4*>(truths)[b * N + lane];
                int ct = labels[b * N + lane] + 1;
                C += lse - crow[ct];
                float gx = ((tt.x + tt.z) * 0.5f - pr.x) * izx;
                float gy = ((tt.y + tt.w) * 0.5f - pr.y) * izy;
                float gw = __logf(__fdividef(tt.z - tt.x, pr.z)) * 5.0f;
                float gh = __logf(__fdividef(tt.w - tt.y, pr.w)) * 5.0f;
                L += smooth_l1(ld.x - gx) + smooth_l1(ld.y - gy)
                   + smooth_l1(ld.z - gw) + smooth_l1(ld.w - gh);
                n += 1;
            }
            // subtract k_post's version if it was already counted
            if (mm < 0) {
                int bnn = mm & 0x7FFFFFFF;
                float4 tt = reinterpret_cast<const float4*>(truths)[b * N + bnn];
                int ct = labels[b * N + bnn] + 1;
                C -= lse - crow[ct];
                float gx = ((tt.x + tt.z) * 0.5f - pr.x) * izx;
                float gy = ((tt.y + tt.w) * 0.5f - pr.y) * izy;
                float gw = __logf(__fdividef(tt.z - tt.x, pr.z)) * 5.0f;
                float gh = __logf(__fdividef(tt.w - tt.y, pr.w)) * 5.0f;
                L -= smooth_l1(ld.x - gx) + smooth_l1(ld.y - gy)
                   + smooth_l1(ld.z - gw) + smooth_l1(ld.w - gh);
                n -= 1;
            }
            g_mine[(size_t)b * P + p] = 0.f;   // exclude from mining
        }
        #pragma unroll
        for (int o = 16; o; o >>= 1) {
            L += __shfl_down_sync(0xFFFFFFFFu, L, o);
            C += __shfl_down_sync(0xFFFFFFFFu, C, o);
            n += __shfl_down_sync(0xFFFFFFFFu, n, o);
        }
        if (lane == 0) { s_np = n; s_k = min(3 * n, P - 1); s_L = L; s_Cp = C; }
    }
    __syncthreads();   // orders warp0's g_mine zero-writes before the loads below
    int k = s_k;

    // load values (order-free)
    const int V4 = 12;
    float4 v4[V4];
    {
        const float4* src = reinterpret_cast<const float4*>(g_mine + (size_t)b * P);
        int n4 = P >> 2;
        #pragma unroll
        for (int i = 0; i < V4; ++i) {
            int j = tid + i * 512;
            v4[i] = (j < n4) ? src[j] : make_float4(0.f, 0.f, 0.f, 0.f);
        }
    }
    int tail = P & 3;
    float vex = 0.f;
    if (tid < tail) vex = g_mine[(size_t)b * P + (P & ~3) + tid];

    // pass 1: histogram of top 12 value bits
    {
        const float* vv = reinterpret_cast<const float*>(v4);
        #pragma unroll
        for (int i = 0; i < 48; ++i) {
            unsigned bin = __float_as_uint(vv[i]) >> 19;
            unsigned m = __match_any_sync(0xFFFFFFFFu, bin);
            if (lane == (__ffs(m) - 1)) atomicAdd(&s_hist[bin], __popc(m));
        }
        if (tid < tail) atomicAdd(&s_hist[__float_as_uint(vex) >> 19], 1);
    }
    __syncthreads();
    find_threshold(s_hist, k, tid, s_wt, s_out);
    unsigned Bs = (unsigned)s_out[0];
    int c1 = s_out[1];

    #pragma unroll
    for (int i = 0; i < 8; ++i) s_hist[tid + i * 512] = 0;
    __syncthreads();

    // pass 2: next 12 bits within bin Bs
    {
        const float* vv = reinterpret_cast<const float*>(v4);
        #pragma unroll
        for (int i = 0; i < 48; ++i) {
            unsigned bits = __float_as_uint(vv[i]);
            if ((bits >> 19) == Bs) atomicAdd(&s_hist[(bits >> 7) & 0xFFF], 1);
        }
        unsigned bx = __float_as_uint(vex);
        if (tid < tail && (bx >> 19) == Bs) atomicAdd(&s_hist[(bx >> 7) & 0xFFF], 1);
    }
    __syncthreads();
    find_threshold(s_hist, k - c1, tid, s_wt, s_out);
    unsigned Ss = (unsigned)s_out[0];

    unsigned Tcut = (Bs << 12) | Ss;
    float Tf = __uint_as_float((Bs << 19) | (Ss << 7));

    float sum = 0.f; int cnt = 0;
    {
        const float* vv = reinterpret_cast<const float*>(v4);
        #pragma unroll
        for (int i = 0; i < 48; ++i) {
            unsigned bits = __float_as_uint(vv[i]);
            if ((bits >> 7) > Tcut) { sum += vv[i]; cnt++; }
        }
        unsigned bx = __float_as_uint(vex);
        if (tid < tail && (bx >> 7) > Tcut) { sum += vex; cnt++; }
    }
    #pragma unroll
    for (int o = 16; o; o >>= 1) {
        sum += __shfl_down_sync(0xFFFFFFFFu, sum, o);
        cnt += __shfl_down_sync(0xFFFFFFFFu, cnt, o);
    }
    if (lane == 0) { s_fs[w] = sum; s_cs[w] = cnt; }
    __syncthreads();
    if (tid == 0) {
        float S = 0.f; int C = 0;
        #pragma unroll
        for (int i = 0; i < 16; ++i) { S += s_fs[i]; C += s_cs[i]; }
        g_bl[b] = s_L;
        g_bc[b] = s_Cp + S + (float)(k - C) * Tf;
        g_bn[b] = s_np;
        __threadfence();
        s_last = (atomicAdd(&g_ctr, 1) == (int)gridDim.x - 1) ? 1 : 0;
    }
    __syncthreads();

    if (s_last) {
        int B = gridDim.x;
        float l = 0.f, c = 0.f, n = 0.f;
        if (tid < 64 && tid < B) {
            l = g_bl[tid]; c = g_bc[tid]; n = (float)g_bn[tid];
        }
        if (tid < 64) {
            #pragma unroll
            for (int o = 16; o; o >>= 1) {
                l += __shfl_down_sync(0xFFFFFFFFu, l, o);
                c += __shfl_down_sync(0xFFFFFFFFu, c, o);
                n += __shfl_down_sync(0xFFFFFFFFu, n, o);
            }
            if (lane == 0) { s_fs[w] = l; s_fs[w + 8] = c; s_fs[w + 4] = n; }
        }
        __syncthreads();
        if (tid == 0) {
            float L = s_fs[0] + s_fs[1];
            float C = s_fs[8] + s_fs[9];
            float NN = s_fs[4] + s_fs[5];
            out[0] = L / NN;
            out[1] = C / NN;
            g_ctr = 0;
        }
    }
}

// ==========================================================================
extern "C" void kernel_launch(void* const* d_in, const int* in_sizes, int n_in,
                              void* d_out, int out_size)
{
    const float* loc    = (const float*)d_in[0];
    const float* conf   = (const float*)d_in[1];
    const float* priors = (const float*)d_in[2];
    const float* truths = (const float*)d_in[3];
    const int*   labels = (const int*)d_in[4];

    int P = in_sizes[2] / 4;
    int B = in_sizes[0] / (4 * P);
    int N = in_sizes[3] / (4 * B);

    int nA = (P + MROWS - 1) / MROWS;    // 16
    int nB = (P + LROWS - 1) / LROWS;    // 24
    int nC = (P + CROWS - 1) / CROWS;    // 8

    dim3 fgrid(nA + nB, B);
    k_fused<<<fgrid, 256>>>(conf, priors, truths, P, N, nA);
    dim3 cgrid(nC, B);
    k_post<<<cgrid, CTPB>>>(loc, conf, priors, truths, labels, P, N);
    k_select<<<B, 512>>>(loc, conf, priors, truths, labels, P, N, nA, (float*)d_out);
}